// round 3
// baseline (speedup 1.0000x reference)
#include <cuda_runtime.h>
#include <math.h>

#define NB 262144
#define NP 8
#define NTHREADS 256
#define NBLOCKS (NB / NTHREADS)

__device__ double g_part[NBLOCKS];

__global__ void __launch_bounds__(NTHREADS)
ciou_kernel(const float* __restrict__ A, const float* __restrict__ Bm) {
    int b = blockIdx.x * blockDim.x + threadIdx.x;

    double val = 0.0;
    {
        // ---- load both octagons (16 floats each, 4x float4) ----
        float axv[NP], ayv[NP], bxv[NP], byv[NP];
        const float4* pa4 = (const float4*)(A  + (size_t)b * 16);
        const float4* pb4 = (const float4*)(Bm + (size_t)b * 16);
        #pragma unroll
        for (int i = 0; i < 4; i++) {
            float4 fa = pa4[i], fb = pb4[i];
            axv[2*i]   = fa.x; ayv[2*i]   = fa.y;
            axv[2*i+1] = fa.z; ayv[2*i+1] = fa.w;
            bxv[2*i]   = fb.x; byv[2*i]   = fb.y;
            bxv[2*i+1] = fb.z; byv[2*i+1] = fb.w;
        }

        // ---- shoelace areas (vertices are CCW by construction) ----
        float area_a = 0.f, area_b = 0.f;
        #pragma unroll
        for (int i = 0; i < NP; i++) {
            int j = (i + 1) & 7;
            area_a += axv[i]*ayv[j] - ayv[i]*axv[j];
            area_b += bxv[i]*byv[j] - byv[i]*bxv[j];
        }
        area_a *= 0.5f; area_b *= 0.5f;

        // ---- edge vectors ----
        float eax[NP], eay[NP], ebx[NP], eby[NP];
        #pragma unroll
        for (int j = 0; j < NP; j++) {
            int k = (j + 1) & 7;
            eax[j] = axv[k] - axv[j]; eay[j] = ayv[k] - ayv[j];
            ebx[j] = bxv[k] - bxv[j]; eby[j] = byv[k] - byv[j];
        }

        // ---- candidate points for intersection polygon ----
        float cx[80], cy[80];
        int   cnt = 0;
        float sx = 0.f, sy = 0.f;

        // vertices of A inside B
        #pragma unroll
        for (int i = 0; i < NP; i++) {
            bool in = true;
            #pragma unroll
            for (int j = 0; j < NP; j++) {
                float cr = ebx[j]*(ayv[i]-byv[j]) - eby[j]*(axv[i]-bxv[j]);
                in = in && (cr >= -1e-6f);
            }
            if (in) { cx[cnt]=axv[i]; cy[cnt]=ayv[i]; sx+=axv[i]; sy+=ayv[i]; cnt++; }
        }
        // vertices of B inside A
        #pragma unroll
        for (int i = 0; i < NP; i++) {
            bool in = true;
            #pragma unroll
            for (int j = 0; j < NP; j++) {
                float cr = eax[j]*(byv[i]-ayv[j]) - eay[j]*(bxv[i]-axv[j]);
                in = in && (cr >= -1e-6f);
            }
            if (in) { cx[cnt]=bxv[i]; cy[cnt]=byv[i]; sx+=bxv[i]; sy+=byv[i]; cnt++; }
        }
        // edge-edge intersections (same order as reference: i over A edges, j over B edges)
        #pragma unroll 2
        for (int i = 0; i < NP; i++) {
            float p1x = axv[i], p1y = ayv[i];
            float d1x = eax[i], d1y = eay[i];
            #pragma unroll
            for (int j = 0; j < NP; j++) {
                float d2x = ebx[j], d2y = eby[j];
                float denom = d1x*d2y - d1y*d2x;
                if (fabsf(denom) >= 1e-9f) {
                    float rx = bxv[j] - p1x, ry = byv[j] - p1y;
                    float t = (rx*d2y - ry*d2x) / denom;
                    float u = (rx*d1y - ry*d1x) / denom;
                    if (t >= 0.f && t <= 1.f && u >= 0.f && u <= 1.f) {
                        float ix = p1x + t*d1x, iy = p1y + t*d1y;
                        cx[cnt]=ix; cy[cnt]=iy; sx+=ix; sy+=iy; cnt++;
                    }
                }
            }
        }

        // ---- intersection area: angular sort around centroid + shoelace ----
        float inter = 0.f;
        if (cnt >= 3) {
            float inv = 1.f / (float)cnt;
            float ctx = sx * inv, cty = sy * inv;
            float ang[80];
            for (int i = 0; i < cnt; i++) ang[i] = atan2f(cy[i]-cty, cx[i]-ctx);
            // stable insertion sort by angle (matches jnp.argsort stability)
            for (int i = 1; i < cnt; i++) {
                float a0 = ang[i], x0 = cx[i], y0 = cy[i];
                int j = i - 1;
                while (j >= 0 && ang[j] > a0) {
                    ang[j+1]=ang[j]; cx[j+1]=cx[j]; cy[j+1]=cy[j]; j--;
                }
                ang[j+1]=a0; cx[j+1]=x0; cy[j+1]=y0;
            }
            float s = 0.f;
            for (int i = 0; i < cnt; i++) {
                int j = (i + 1 == cnt) ? 0 : i + 1;
                s += cx[i]*cy[j] - cy[i]*cx[j];
            }
            inter = fmaxf(0.5f * s, 0.f);
        }

        // ---- convex hull area of all 16 points (cross-product Jarvis march) ----
        float px_[16], py_[16];
        #pragma unroll
        for (int i = 0; i < NP; i++) {
            px_[i]    = axv[i]; py_[i]    = ayv[i];
            px_[i+NP] = bxv[i]; py_[i+NP] = byv[i];
        }
        int start = 0;
        #pragma unroll
        for (int i = 1; i < 16; i++) {
            if (py_[i] < py_[start] ||
                (py_[i] == py_[start] && px_[i] < px_[start])) start = i;
        }
        float acc = 0.f;
        int cur = start;
        for (int step = 0; step < 16; step++) {
            float cpx = px_[cur], cpy = py_[cur];
            int   nxt = -1;
            float vnx = 0.f, vny = 0.f, nd2 = 0.f;
            #pragma unroll
            for (int p = 0; p < 16; p++) {
                float vx = px_[p] - cpx, vy = py_[p] - cpy;
                float d2 = vx*vx + vy*vy;
                if (d2 < 1e-16f) continue;               // skip coincident points
                if (nxt < 0) { nxt = p; vnx = vx; vny = vy; nd2 = d2; }
                else {
                    float cr = vnx*vy - vny*vx;          // p right of cur->cand?
                    if (cr < 0.f || (cr == 0.f && d2 > nd2)) {
                        nxt = p; vnx = vx; vny = vy; nd2 = d2;
                    }
                }
            }
            if (nxt < 0) break;
            acc += cpx*py_[nxt] - cpy*px_[nxt];
            if (nxt == start) break;
            cur = nxt;
        }
        float ch = 0.5f * acc;

        // ---- CIoU ----
        float uni  = area_a + area_b - inter;
        float iou  = inter / uni;
        float ciou = iou - (ch - uni) / ch;
        val = (double)ciou;
    }

    // ---- deterministic block reduction ----
    #pragma unroll
    for (int o = 16; o > 0; o >>= 1)
        val += __shfl_down_sync(0xffffffffu, val, o);
    __shared__ double ws[NTHREADS / 32];
    int lane = threadIdx.x & 31;
    int w    = threadIdx.x >> 5;
    if (lane == 0) ws[w] = val;
    __syncthreads();
    if (w == 0) {
        val = (lane < (NTHREADS / 32)) ? ws[lane] : 0.0;
        #pragma unroll
        for (int o = 4; o > 0; o >>= 1)
            val += __shfl_down_sync(0xffffffffu, val, o);
        if (lane == 0) g_part[blockIdx.x] = val;
    }
}

__global__ void __launch_bounds__(256)
reduce_kernel(float* __restrict__ out) {
    double v = 0.0;
    // NBLOCKS = 1024, 256 threads -> 4 each
    for (int i = threadIdx.x; i < NBLOCKS; i += 256) v += g_part[i];
    #pragma unroll
    for (int o = 16; o > 0; o >>= 1)
        v += __shfl_down_sync(0xffffffffu, v, o);
    __shared__ double ws[8];
    int lane = threadIdx.x & 31;
    int w    = threadIdx.x >> 5;
    if (lane == 0) ws[w] = v;
    __syncthreads();
    if (w == 0) {
        v = (lane < 8) ? ws[lane] : 0.0;
        #pragma unroll
        for (int o = 4; o > 0; o >>= 1)
            v += __shfl_down_sync(0xffffffffu, v, o);
        if (lane == 0) out[0] = (float)(v / (double)NB);
    }
}

extern "C" void kernel_launch(void* const* d_in, const int* in_sizes, int n_in,
                              void* d_out, int out_size) {
    const float* a = (const float*)d_in[0];
    const float* b = (const float*)d_in[1];
    ciou_kernel<<<NBLOCKS, NTHREADS>>>(a, b);
    reduce_kernel<<<1, 256>>>((float*)d_out);
}